// round 1
// baseline (speedup 1.0000x reference)
#include <cuda_runtime.h>

#define TPB 256
#define NB  5

__device__ __forceinline__ float f_ex2(float x){ float y; asm("ex2.approx.ftz.f32 %0, %1;" : "=f"(y) : "f"(x)); return y; }
__device__ __forceinline__ float f_lg2(float x){ float y; asm("lg2.approx.ftz.f32 %0, %1;" : "=f"(y) : "f"(x)); return y; }
__device__ __forceinline__ float f_rcp(float x){ float y; asm("rcp.approx.ftz.f32 %0, %1;" : "=f"(y) : "f"(x)); return y; }
__device__ __forceinline__ float f_rsq(float x){ float y; asm("rsqrt.approx.ftz.f32 %0, %1;" : "=f"(y) : "f"(x)); return y; }

__global__ __launch_bounds__(TPB)
void klproj_kernel(const float* __restrict__ x,
                   const float* __restrict__ W,
                   const float* __restrict__ b,
                   float* __restrict__ out,
                   int nrows)
{
    __shared__ float sx[TPB * NB];   // 1280 floats staging (in, then out)
    __shared__ float swb[32];        // W (25) + b (5)

    const int tid  = threadIdx.x;
    const int base = blockIdx.x * (TPB * NB);       // fits in int (max ~10.5M)
    const int total = nrows * NB;
    int avail = total - base;
    if (avail > TPB * NB) avail = TPB * NB;

    // ---- stage inputs: coalesced float4 loads into smem ----
    if (avail == TPB * NB) {
        const float4* s4 = reinterpret_cast<const float4*>(x + base);
        float4* d4 = reinterpret_cast<float4*>(sx);
        d4[tid] = s4[tid];                           // 256 of 320
        int i2 = tid + TPB;
        if (i2 < (TPB * NB) / 4) d4[i2] = s4[i2];    // remaining 64
    } else {
        for (int i = tid; i < avail; i += TPB) sx[i] = x[base + i];
    }
    if (tid < 25)      swb[tid] = W[tid];
    else if (tid < 30) swb[tid] = b[tid - 25];
    __syncthreads();

    const int row = base / NB + tid;
    float p[NB];

    if (row < nrows) {
        // ---- load row (stride-5 LDS: gcd(5,32)=1 -> conflict-free) ----
        float xv[NB];
        #pragma unroll
        for (int j = 0; j < NB; j++) xv[j] = sx[tid * NB + j];

        // ---- q = x @ W^T + b ; L = log2(q) ----
        float q[NB], L[NB];
        #pragma unroll
        for (int j = 0; j < NB; j++) {
            float acc = swb[25 + j];
            #pragma unroll
            for (int k = 0; k < NB; k++) acc = fmaf(xv[k], swb[j * NB + k], acc);
            q[j] = acc;
            L[j] = f_lg2(acc);
        }

        const float LOG2_5 = 2.3219280948873623f;
        const float EPS2   = 0.14426950408889634f;   // 0.1 / ln2
        const float LN2    = 0.6931471805599453f;

        // ---- feasibility check at t=1 (2^L == q, no EX2 needed) ----
        float S1 = q[0] + q[1] + q[2] + q[3] + q[4];
        float A1 = 0.f;
        #pragma unroll
        for (int j = 0; j < NB; j++) A1 = fmaf(L[j], q[j], A1);
        float rS1 = f_rcp(S1);
        float KL1 = fmaf(A1, rS1, LOG2_5) - f_lg2(S1);   // base-2 KL(p(1)||u)

        if (KL1 <= EPS2) {
            // feasible: lam = 0, p = q / sum(q)  (matches reference exactly)
            #pragma unroll
            for (int j = 0; j < NB; j++) p[j] = q[j] * rS1;
        } else {
            // ---- Newton on f(t) = KL2(t) - EPS2, f'(t)*t = ln2*rS*(B - A^2 rS) ----
            // init from quadratic model KL ~ c*t^2:  t0 = sqrt(EPS2/KL1)
            float t = f_rsq(KL1 * 6.9314718055994531f);   // = sqrt(EPS2/KL1), since 1/EPS2 = 10*ln2
            t = fminf(fmaxf(t, 1e-3f), 0.999f);
            #pragma unroll
            for (int it = 0; it < 5; ++it) {
                float S = 0.f, A = 0.f, B = 0.f;
                #pragma unroll
                for (int j = 0; j < NB; j++) {
                    float z  = t * L[j];
                    float e  = f_ex2(z);
                    float ze = z * e;
                    S += e;
                    A += ze;
                    B  = fmaf(z, ze, B);
                }
                float rS    = f_rcp(S);
                float fval  = fmaf(A, rS, LOG2_5 - EPS2) - f_lg2(S);
                float denom = LN2 * rS * (B - A * A * rS);   // = f'(t) * t  (= ln2 * Var_p(z) > 0 here)
                t = t - fval * t * f_rcp(denom);
                t = fminf(fmaxf(t, 1e-4f), 1.0f);
            }
            // final p at converged t
            float S = 0.f, e[NB];
            #pragma unroll
            for (int j = 0; j < NB; j++) { e[j] = f_ex2(t * L[j]); S += e[j]; }
            float rS = f_rcp(S);
            #pragma unroll
            for (int j = 0; j < NB; j++) p[j] = e[j] * rS;
        }
    }

    // ---- stage outputs through smem, coalesced float4 stores ----
    __syncthreads();
    if (row < nrows) {
        #pragma unroll
        for (int j = 0; j < NB; j++) sx[tid * NB + j] = p[j];
    }
    __syncthreads();
    if (avail == TPB * NB) {
        float4* o4 = reinterpret_cast<float4*>(out + base);
        const float4* s4 = reinterpret_cast<const float4*>(sx);
        o4[tid] = s4[tid];
        int i2 = tid + TPB;
        if (i2 < (TPB * NB) / 4) o4[i2] = s4[i2];
    } else {
        for (int i = tid; i < avail; i += TPB) out[base + i] = sx[i];
    }
}

extern "C" void kernel_launch(void* const* d_in, const int* in_sizes, int n_in,
                              void* d_out, int out_size)
{
    const float* x = (const float*)d_in[0];
    const float* W = (const float*)d_in[1];
    const float* b = (const float*)d_in[2];
    // robust to W/b ordering: W has 25 elements, b has 5
    if (n_in >= 3 && in_sizes[1] == NB && in_sizes[2] == NB * NB) {
        const float* tmp = W; W = b; b = tmp;
    }
    float* out = (float*)d_out;
    int nrows  = in_sizes[0] / NB;
    int blocks = (nrows + TPB - 1) / TPB;
    klproj_kernel<<<blocks, TPB>>>(x, W, b, out, nrows);
}